// round 8
// baseline (speedup 1.0000x reference)
#include <cuda_runtime.h>
#include <cuda_fp16.h>

// ---------------------------------------------------------------------------
// WavePlaneField: 6 planes reconstructed via 2-level inverse DWT (coif4,
// periodization), bilinear-sampled at N points, channelwise product.
//
// Phase 1 (4 kernels): separable inverse DWT per plane -> g_planes2, an
//   x-paired fp16 layout: element (y,x,c) = half2(v[y,x,c], v[y,x+1,c]).
// Phase 1b: per-point coordinate kernel (dedups lane-uniform coord math).
// Phase 2: warp-per-point sampler: 6 broadcast coord loads + 12 half2 loads.
// ---------------------------------------------------------------------------

#define CCH 32
#define CSTRIDE 524288   // max points stride for coord buffer

// All planes have H=256. W per plane:
__constant__ int c_W[6]    = {256, 256, 64, 256, 64, 64};
__constant__ int c_POFF[6] = {0, 65536, 131072, 147456, 212992, 229376}; // pixel offsets

// coif4 reconstruction filters (24 taps)
__constant__ float REC_LO_C[24] = {
    0.0008923136685823146f, -0.0016294920126017326f, -0.0073461663276420935f,
    0.016068943964776348f, 0.026682300156053072f, -0.08126669968087875f,
    -0.05607731331675481f, 0.41530840703043026f, 0.782238930920499f,
    0.4343860564914685f, -0.06662747426342504f, -0.09622044203398798f,
    0.03933442712333749f, 0.025082261844864097f, -0.015211731527946259f,
    -0.00565828668661072f, 0.003751436157278457f, 0.0012665619292989445f,
    -0.0005890207562443383f, -0.00025997455248771324f, 6.233903446100713e-05f,
    3.1229875865345646e-05f, -3.2596802368833675e-06f, -1.7849850030882614e-06f
};
__constant__ float REC_HI_C[24] = {
    -1.7849850030882614e-06f, 3.2596802368833675e-06f, 3.1229875865345646e-05f,
    -6.233903446100713e-05f, -0.00025997455248771324f, 0.0005890207562443383f,
    0.0012665619292989445f, -0.003751436157278457f, -0.00565828668661072f,
    0.015211731527946259f, 0.025082261844864097f, -0.03933442712333749f,
    -0.09622044203398798f, 0.06662747426342504f, 0.4343860564914685f,
    -0.782238930920499f, 0.41530840703043026f, 0.05607731331675481f,
    -0.08126669968087875f, -0.026682300156053072f, 0.016068943964776348f,
    0.0073461663276420935f, -0.0016294920126017326f, -0.0008923136685823146f
};

// Scratch (static device globals; per-plane strides sized for the largest plane)
#define S_LO1 262144    // C*128*64
#define S_MID 524288    // C*128*128
#define S_LO2 1048576   // C*256*128
__device__ float g_lo1[6 * S_LO1];
__device__ float g_hi1[6 * S_LO1];
__device__ float g_mid[6 * S_MID];
__device__ float g_lo2[6 * S_LO2];
__device__ float g_hi2[6 * S_LO2];
// x-paired fp16 planes: [pixel][c] = half2(v[y,x,c], v[y,min(x+1,W-1),c])
__device__ __half2 g_planes2[245760 * CCH];
// per (plane, point): {__int_as_float(base_idx), wx, wy, 0}
__device__ float4 g_coord[6 * CSTRIDE];

struct CoefPtrs {
    const float* yl[6];
    const float* yha[6];
    const float* yhb[6];
};

// Stage 1: level-1 H-axis synthesis. in: yl[C,64,w4], yhb[C,3,64,w4]
// out: lo1,hi1 [C,128,w4]
__global__ void k_stage1(CoefPtrs P) {
    const int pl = blockIdx.y;
    const int w4 = c_W[pl] >> 2;
    const int n = CCH * 128 * w4;
    const int tid = blockIdx.x * blockDim.x + threadIdx.x;
    if (tid >= n) return;
    const int x = tid % w4;
    const int i = (tid / w4) & 127;
    const int c = tid / (w4 * 128);
    const int s = i >> 1, p = i & 1;
    const float* yl = P.yl[pl];
    const float* yhb = P.yhb[pl];
    const int bandStride = 64 * w4;
    float lo = 0.f, hi = 0.f;
#pragma unroll
    for (int m = 0; m < 12; m++) {
        int row = s - m; if (row < 0) row += 64;
        const float fl = REC_LO_C[2 * m + p];
        const float fh = REC_HI_C[2 * m + p];
        const int bi = (c * 64 + row) * w4 + x;
        const int b0 = ((c * 3 + 0) * 64 + row) * w4 + x;
        lo += fl * yl[bi] + fh * yhb[b0];
        hi += fl * yhb[b0 + bandStride] + fh * yhb[b0 + 2 * bandStride];
    }
    g_lo1[pl * S_LO1 + tid] = lo;
    g_hi1[pl * S_LO1 + tid] = hi;
}

// Stage 2: level-1 W-axis synthesis. in: lo1,hi1 [C,128,w4] -> mid [C,128,w2]
__global__ void k_stage2() {
    const int pl = blockIdx.y;
    const int w2 = c_W[pl] >> 1;
    const int w4 = w2 >> 1;
    const int n = CCH * 128 * w2;
    const int tid = blockIdx.x * blockDim.x + threadIdx.x;
    if (tid >= n) return;
    const int j = tid % w2;
    const int i = (tid / w2) & 127;
    const int c = tid / (w2 * 128);
    const int s = j >> 1, p = j & 1;
    const int base = pl * S_LO1 + (c * 128 + i) * w4;
    float v = 0.f;
#pragma unroll
    for (int m = 0; m < 12; m++) {
        int col = s - m; if (col < 0) col += w4;
        v += REC_LO_C[2 * m + p] * g_lo1[base + col]
           + REC_HI_C[2 * m + p] * g_hi1[base + col];
    }
    g_mid[pl * S_MID + tid] = v;
}

// Stage 3: level-2 H-axis synthesis. in: mid [C,128,w2], yha [C,3,128,w2]
// out: lo2,hi2 [C,256,w2]
__global__ void k_stage3(CoefPtrs P) {
    const int pl = blockIdx.y;
    const int w2 = c_W[pl] >> 1;
    const int n = CCH * 256 * w2;
    const int tid = blockIdx.x * blockDim.x + threadIdx.x;
    if (tid >= n) return;
    const int x = tid % w2;
    const int i = (tid / w2) & 255;
    const int c = tid / (w2 * 256);
    const int s = i >> 1, p = i & 1;
    const float* yha = P.yha[pl];
    const int bandStride = 128 * w2;
    const int midBase = pl * S_MID;
    float lo = 0.f, hi = 0.f;
#pragma unroll
    for (int m = 0; m < 12; m++) {
        int row = s - m; if (row < 0) row += 128;
        const float fl = REC_LO_C[2 * m + p];
        const float fh = REC_HI_C[2 * m + p];
        const int bi = (c * 128 + row) * w2 + x;
        const int b0 = ((c * 3 + 0) * 128 + row) * w2 + x;
        lo += fl * g_mid[midBase + bi] + fh * yha[b0];
        hi += fl * yha[b0 + bandStride] + fh * yha[b0 + 2 * bandStride];
    }
    g_lo2[pl * S_LO2 + tid] = lo;
    g_hi2[pl * S_LO2 + tid] = hi;
}

// Stage 4 (row-tiled, paired-parity, x-paired output): level-2 W-axis
// synthesis + transpose to x-paired half2 layout. One block per (plane, y).
// Compute phase: thread -> (c, s), emits parity-0/1 outputs into smem.
// Write phase: pack (v[x], v[x+1]) as half2, coalesced.
__global__ void __launch_bounds__(256) k_stage4() {
    const int pl = blockIdx.y;
    const int W = c_W[pl];
    const int w2 = W >> 1;
    const int y = blockIdx.x;

    __shared__ float lo_s[32][129];
    __shared__ float hi_s[32][129];
    __shared__ float out_s[256][33];   // [x][c]

    const int sh = (w2 == 128) ? 7 : 5;          // log2(w2)
    const int rowBase = pl * S_LO2 + y * w2;     // + c*256*w2 per channel
    for (int t = threadIdx.x; t < 32 * w2; t += 256) {
        const int c = t >> sh;
        const int col = t & (w2 - 1);
        const int gi = rowBase + c * (256 * w2) + col;
        lo_s[c][col] = g_lo2[gi];
        hi_s[c][col] = g_hi2[gi];
    }
    __syncthreads();

    const int nPairs = w2 * CCH;                  // one thread -> 2 outputs
    for (int t = threadIdx.x; t < nPairs; t += 256) {
        const int c = t & 31;                     // = lane
        const int s = t >> 5;
        float v0 = 0.f, v1 = 0.f;                 // parity 0 / parity 1
#pragma unroll
        for (int m = 0; m < 12; m++) {
            int col = s - m; if (col < 0) col += w2;
            const float lv = lo_s[c][col];
            const float hv = hi_s[c][col];
            v0 += REC_LO_C[2 * m]     * lv + REC_HI_C[2 * m]     * hv;
            v1 += REC_LO_C[2 * m + 1] * lv + REC_HI_C[2 * m + 1] * hv;
        }
        out_s[2 * s][c]     = v0;
        out_s[2 * s + 1][c] = v1;
    }
    __syncthreads();

    __half2* __restrict__ outRow = g_planes2 + ((size_t)(c_POFF[pl] + y * W)) * CCH;
    const int n = W * CCH;
    for (int t = threadIdx.x; t < n; t += 256) {
        const int c = t & 31;
        const int x = t >> 5;
        const int x1 = (x + 1 < W) ? x + 1 : W - 1;
        outRow[x * CCH + c] = __floats2half2_rn(out_s[x][c], out_s[x1][c]);
    }
}

// Phase 1b: per-point coordinate precompute (one thread per point).
__global__ void __launch_bounds__(256) k_coords(const float* __restrict__ pts,
                                                const float* __restrict__ ts,
                                                int nPts) {
    const int i = blockIdx.x * blockDim.x + threadIdx.x;
    if (i >= nPts) return;

    const float inv = -1.0f / 1.3f;   // pts_n = -pts/B
    float p4[4];
    p4[0] = pts[i * 3 + 0] * inv;
    p4[1] = pts[i * 3 + 1] * inv;
    p4[2] = pts[i * 3 + 2] * inv;
    p4[3] = ts[i] * 2.0f - 1.0f;

    constexpr int QIDX[6] = {0, 0, 3, 1, 3, 3};
    constexpr int RIDX[6] = {1, 2, 0, 2, 1, 2};
    constexpr int PW[6]   = {256, 256, 64, 256, 64, 64};
    constexpr int POFF[6] = {0, 65536, 131072, 147456, 212992, 229376};

#pragma unroll
    for (int ii = 0; ii < 6; ii++) {
        const int W = PW[ii];
        const float cx = p4[QIDX[ii]];
        const float cy = p4[RIDX[ii]];
        float xf = fminf(fmaxf((cx + 1.0f) * 0.5f * (float)(W - 1), 0.0f), (float)(W - 1));
        float yf = fminf(fmaxf((cy + 1.0f) * 0.5f * 255.0f, 0.0f), 255.0f);
        float x0f = fminf(fmaxf(floorf(xf), 0.0f), (float)(W - 2));
        float y0f = fminf(fmaxf(floorf(yf), 0.0f), 254.0f);
        const float wx = xf - x0f;
        const float wy = yf - y0f;
        const int base = (POFF[ii] + (int)y0f * W + (int)x0f) * CCH;
        g_coord[ii * CSTRIDE + i] = make_float4(__int_as_float(base), wx, wy, 0.0f);
    }
}

// Phase 2: warp per point, lane = channel. 6 broadcast coord loads +
// 12 half2 plane loads per point (x-corners paired in one load).
__global__ void __launch_bounds__(256) k_sample(float* __restrict__ out,
                                                int nPts) {
    const int warp = (blockIdx.x * blockDim.x + threadIdx.x) >> 5;
    const int lane = threadIdx.x & 31;
    if (warp >= nPts) return;

    constexpr int PW[6] = {256, 256, 64, 256, 64, 64};

    float prod = 1.0f;
#pragma unroll
    for (int ii = 0; ii < 6; ii++) {
        const float4 cd = g_coord[ii * CSTRIDE + warp];   // lane-uniform
        const int i00 = __float_as_int(cd.x) + lane;
        const float wx = cd.y;
        const float wy = cd.z;
        const __half2 a = g_planes2[i00];                  // (v00, v01)
        const __half2 b = g_planes2[i00 + PW[ii] * CCH];   // (v10, v11)
        const float2 fa = __half22float2(a);
        const float2 fb = __half22float2(b);
        const float r0 = fa.x + wx * (fa.y - fa.x);
        const float r1 = fb.x + wx * (fb.y - fb.x);
        prod *= r0 + wy * (r1 - r0);
    }
    out[(size_t)warp * CCH + lane] = prod;
}

extern "C" void kernel_launch(void* const* d_in, const int* in_sizes, int n_in,
                              void* d_out, int out_size) {
    const float* pts = (const float*)d_in[0];
    const float* ts  = (const float*)d_in[1];
    CoefPtrs P;
    for (int i = 0; i < 6; i++) {
        P.yl[i]  = (const float*)d_in[2 + 3 * i];
        P.yha[i] = (const float*)d_in[3 + 3 * i];
        P.yhb[i] = (const float*)d_in[4 + 3 * i];
    }
    float* out = (float*)d_out;
    const int nPts = in_sizes[1];   // timestamps count = N

    dim3 blk(256);
    k_stage1<<<dim3((CCH * 128 * 64 + 255) / 256, 6), blk>>>(P);
    k_stage2<<<dim3((CCH * 128 * 128 + 255) / 256, 6), blk>>>();
    k_stage3<<<dim3((CCH * 256 * 128 + 255) / 256, 6), blk>>>(P);
    k_stage4<<<dim3(256, 6), blk>>>();
    k_coords<<<(nPts + 255) / 256, blk>>>(pts, ts, nPts);

    const int totalThreads = nPts * 32;
    k_sample<<<(totalThreads + 255) / 256, 256>>>(out, nPts);
}